// round 1
// baseline (speedup 1.0000x reference)
#include <cuda_runtime.h>

// Problem constants
#define BATCH 32
#define SEQ   2048
#define NPOS  (BATCH * SEQ)   // 65536 positions
#define M     10              // number of primes
#define NTAB  129             // sum of primes 2+3+5+7+11+13+17+19+23+29

// Tables (filled every launch by init kernel; deterministic, graph-capturable)
// g_tabW: { K*cos, K*cos, K*sin, K*sin }  with K = TEMP * log2(e)  (softmax logits in log2 domain)
// g_tabE: { cos, cos, sin, sin }          (re-encode templates)
__device__ float4 g_tabW[NTAB];
__device__ float4 g_tabE[NTAB];

__global__ void init_tables_kernel() {
    int idx = threadIdx.x;
    if (idx >= NTAB) return;
    const int primes[M] = {2, 3, 5, 7, 11, 13, 17, 19, 23, 29};
    int k = idx, p = 29;
    for (int pi = 0; pi < M; pi++) {
        if (k < primes[pi]) { p = primes[pi]; break; }
        k -= primes[pi];
    }
    double ang = 6.283185307179586476925287 * (double)k / (double)p;
    double cd = cos(ang), sd = sin(ang);
    float c = (float)cd, s = (float)sd;     // matches numpy float64 -> float32 rounding
    const double K = 1000.0 * 1.4426950408889634074;  // TEMP * log2(e)
    float cK = (float)((double)c * K);
    float sK = (float)((double)s * K);
    g_tabW[idx] = make_float4(cK, cK, sK, sK);
    g_tabE[idx] = make_float4(c, c, s, s);
}

// ---- packed f32x2 helpers (Blackwell FFMA2 path; only reachable via PTX) ----
union F2U { float2 f; unsigned long long u; };

__device__ __forceinline__ float2 f2fma(float2 a, float2 b, float2 c) {
    F2U A, B, C, D; A.f = a; B.f = b; C.f = c;
    asm("fma.rn.f32x2 %0, %1, %2, %3;" : "=l"(D.u) : "l"(A.u), "l"(B.u), "l"(C.u));
    return D.f;
}
__device__ __forceinline__ float2 f2mul(float2 a, float2 b) {
    F2U A, B, D; A.f = a; B.f = b;
    asm("mul.rn.f32x2 %0, %1, %2;" : "=l"(D.u) : "l"(A.u), "l"(B.u));
    return D.f;
}
__device__ __forceinline__ float2 f2add(float2 a, float2 b) {
    F2U A, B, D; A.f = a; B.f = b;
    asm("add.rn.f32x2 %0, %1, %2;" : "=l"(D.u) : "l"(A.u), "l"(B.u));
    return D.f;
}
__device__ __forceinline__ float ex2f(float x) {
    float r; asm("ex2.approx.f32 %0, %1;" : "=f"(r) : "f"(x)); return r;
}
__device__ __forceinline__ float rcpf(float x) {
    float r; asm("rcp.approx.f32 %0, %1;" : "=f"(r) : "f"(x)); return r;
}

// Softmax weights (unnormalized, max-subtracted) for one circle input, two positions packed.
// c2/s2 hold (cos,sin) components for position 0 (lane x) and position 1 (lane y).
// Logits are computed directly in the log2 domain (tables pre-scaled by TEMP*log2e).
// Returns packed sum of weights.
template <int P>
__device__ __forceinline__ float2 soft_weights(float2 c2, float2 s2,
                                               const float4* tw, float2 w[]) {
#pragma unroll
    for (int i = 0; i < P; i++) {
        float4 t = tw[i];
        w[i] = f2fma(c2, make_float2(t.x, t.y), f2mul(s2, make_float2(t.z, t.w)));
    }
    float mx0 = w[0].x, mx1 = w[0].y;
#pragma unroll
    for (int i = 1; i < P; i++) { mx0 = fmaxf(mx0, w[i].x); mx1 = fmaxf(mx1, w[i].y); }
    float2 nmx = make_float2(-mx0, -mx1);
    float2 S = make_float2(0.f, 0.f);
#pragma unroll
    for (int i = 0; i < P; i++) {
        float2 arg = f2add(w[i], nmx);
        float2 e = make_float2(ex2f(arg.x), ex2f(arg.y));
        w[i] = e;
        S = f2add(S, e);
    }
    return S;
}

template <int P, int PI, int OFF>
__device__ __forceinline__ void do_prime(
    const float2* __restrict__ a2, const float2* __restrict__ b2,
    float2* __restrict__ oAdd, float2* __restrict__ oSub, float2* __restrict__ oMul,
    int pos0, const float4* shW, const float4* shE)
{
    const int i0 = pos0 * M + PI;
    const int i1 = i0 + M;   // next position, same prime
    float2 A0 = a2[i0], A1 = a2[i1];
    float2 B0 = b2[i0], B1 = b2[i1];

    // add = a+b on circle, sub = a-b (conj b) -- share the 4 products
    {
        float t1 = A0.x * B0.x, t2 = A0.y * B0.y, t3 = A0.y * B0.x, t4 = A0.x * B0.y;
        oAdd[i0] = make_float2(t1 - t2, t3 + t4);
        oSub[i0] = make_float2(t1 + t2, t3 - t4);
    }
    {
        float t1 = A1.x * B1.x, t2 = A1.y * B1.y, t3 = A1.y * B1.x, t4 = A1.x * B1.y;
        oAdd[i1] = make_float2(t1 - t2, t3 + t4);
        oSub[i1] = make_float2(t1 + t2, t3 - t4);
    }

    // pack two positions into f32x2 lanes
    float2 ca = make_float2(A0.x, A1.x), sa = make_float2(A0.y, A1.y);
    float2 cb = make_float2(B0.x, B1.x), sb = make_float2(B0.y, B1.y);

    float2 wa[P], wb[P];
    float2 Sa = soft_weights<P>(ca, sa, shW + OFF, wa);
    float2 Sb = soft_weights<P>(cb, sb, shW + OFF, wb);

    float2 dist[P];
    // all i=0 / j=0 contributions land on residue 0 (closed form, avoids serialized chain)
    {
        float2 nwb0 = make_float2(-wb[0].x, -wb[0].y);
        dist[0] = f2fma(wa[0], Sb, f2fma(wb[0], Sa, f2mul(wa[0], nwb0)));
    }
#pragma unroll
    for (int k = 1; k < P; k++) dist[k] = make_float2(0.f, 0.f);
    // i,j >= 1: (i*j)%P is a bijection over 1..P-1 for fixed i (P prime)
#pragma unroll
    for (int i = 1; i < P; i++) {
#pragma unroll
        for (int j = 1; j < P; j++) {
            const int k = (i * j) % P;
            dist[k] = f2fma(wa[i], wb[j], dist[k]);
        }
    }

    // re-encode to circle and normalize by (sum wa)*(sum wb)
    float2 X = make_float2(0.f, 0.f), Y = make_float2(0.f, 0.f);
#pragma unroll
    for (int k = 0; k < P; k++) {
        float4 t = shE[OFF + k];
        X = f2fma(dist[k], make_float2(t.x, t.y), X);
        Y = f2fma(dist[k], make_float2(t.z, t.w), Y);
    }
    float2 Z = f2mul(Sa, Sb);
    float2 inv = make_float2(rcpf(Z.x), rcpf(Z.y));
    X = f2mul(X, inv);
    Y = f2mul(Y, inv);
    oMul[i0] = make_float2(X.x, Y.x);
    oMul[i1] = make_float2(X.y, Y.y);
}

__global__ void __launch_bounds__(64)
circle_kernel(const float* __restrict__ a, const float* __restrict__ b,
              float* __restrict__ out)
{
    __shared__ float4 shW[NTAB];
    __shared__ float4 shE[NTAB];
    for (int i = threadIdx.x; i < NTAB; i += 64) {
        shW[i] = g_tabW[i];
        shE[i] = g_tabE[i];
    }
    __syncthreads();

    int t = blockIdx.x * 64 + threadIdx.x;
    if (t >= NPOS / 2) return;
    int pos0 = 2 * t;

    const float2* a2 = (const float2*)a;
    const float2* b2 = (const float2*)b;
    float2* oAdd = (float2*)out;
    float2* oSub = oAdd + (size_t)NPOS * M;
    float2* oMul = oSub + (size_t)NPOS * M;

    do_prime< 2, 0,   0>(a2, b2, oAdd, oSub, oMul, pos0, shW, shE);
    do_prime< 3, 1,   2>(a2, b2, oAdd, oSub, oMul, pos0, shW, shE);
    do_prime< 5, 2,   5>(a2, b2, oAdd, oSub, oMul, pos0, shW, shE);
    do_prime< 7, 3,  10>(a2, b2, oAdd, oSub, oMul, pos0, shW, shE);
    do_prime<11, 4,  17>(a2, b2, oAdd, oSub, oMul, pos0, shW, shE);
    do_prime<13, 5,  28>(a2, b2, oAdd, oSub, oMul, pos0, shW, shE);
    do_prime<17, 6,  41>(a2, b2, oAdd, oSub, oMul, pos0, shW, shE);
    do_prime<19, 7,  58>(a2, b2, oAdd, oSub, oMul, pos0, shW, shE);
    do_prime<23, 8,  77>(a2, b2, oAdd, oSub, oMul, pos0, shW, shE);
    do_prime<29, 9, 100>(a2, b2, oAdd, oSub, oMul, pos0, shW, shE);
}

extern "C" void kernel_launch(void* const* d_in, const int* in_sizes, int n_in,
                              void* d_out, int out_size) {
    const float* a = (const float*)d_in[0];
    const float* b = (const float*)d_in[1];
    float* out = (float*)d_out;
    init_tables_kernel<<<1, 160>>>();
    circle_kernel<<<(NPOS / 2) / 64, 64>>>(a, b, out);
}

// round 2
// speedup vs baseline: 1.3144x; 1.3144x over previous
#include <cuda_runtime.h>

// Problem constants
#define BATCH 32
#define SEQ   2048
#define NPOS  (BATCH * SEQ)   // 65536 positions
#define M     10              // number of primes
#define NTAB  129             // sum of primes 2+3+5+7+11+13+17+19+23+29

// Tables (filled every launch by init kernel; deterministic, graph-capturable)
// g_tabW: { K*cos, K*cos, K*sin, K*sin }  with K = TEMP * log2(e)  (softmax logits in log2 domain)
// g_tabE: { cos, sin }                    (re-encode templates)
__device__ float4 g_tabW[NTAB];
__device__ float2 g_tabE[NTAB];

__global__ void init_tables_kernel() {
    int idx = threadIdx.x;
    if (idx >= NTAB) return;
    const int primes[M] = {2, 3, 5, 7, 11, 13, 17, 19, 23, 29};
    int k = idx, p = 29;
    for (int pi = 0; pi < M; pi++) {
        if (k < primes[pi]) { p = primes[pi]; break; }
        k -= primes[pi];
    }
    double ang = 6.283185307179586476925287 * (double)k / (double)p;
    float c = (float)cos(ang), s = (float)sin(ang);  // matches numpy f64->f32 rounding
    const double K = 1000.0 * 1.4426950408889634074; // TEMP * log2(e)
    float cK = (float)((double)c * K);
    float sK = (float)((double)s * K);
    g_tabW[idx] = make_float4(cK, cK, sK, sK);
    g_tabE[idx] = make_float2(c, s);
}

// ---- packed f32x2 helpers (Blackwell FFMA2; only reachable via PTX) ----
union F2U { float2 f; unsigned long long u; };

__device__ __forceinline__ float2 f2fma(float2 a, float2 b, float2 c) {
    F2U A, B, C, D; A.f = a; B.f = b; C.f = c;
    asm("fma.rn.f32x2 %0, %1, %2, %3;" : "=l"(D.u) : "l"(A.u), "l"(B.u), "l"(C.u));
    return D.f;
}
__device__ __forceinline__ float2 f2mul(float2 a, float2 b) {
    F2U A, B, D; A.f = a; B.f = b;
    asm("mul.rn.f32x2 %0, %1, %2;" : "=l"(D.u) : "l"(A.u), "l"(B.u));
    return D.f;
}
__device__ __forceinline__ float2 f2add(float2 a, float2 b) {
    F2U A, B, D; A.f = a; B.f = b;
    asm("add.rn.f32x2 %0, %1, %2;" : "=l"(D.u) : "l"(A.u), "l"(B.u));
    return D.f;
}
__device__ __forceinline__ float ex2f(float x) {
    float r; asm("ex2.approx.f32 %0, %1;" : "=f"(r) : "f"(x)); return r;
}
__device__ __forceinline__ float rcpf(float x) {
    float r; asm("rcp.approx.f32 %0, %1;" : "=f"(r) : "f"(x)); return r;
}

// One prime, ONE position per thread. a-side / b-side packed into f32x2 lanes
// (lane x = a, lane y = b) for logits / max-subtract / exp-sum. The p^2 mul-table
// contraction is scalar with (i*j)%P constant-folded targets (full ILP).
template <int P, int PI, int OFF>
__device__ __forceinline__ void do_prime(
    const float2* __restrict__ a2, const float2* __restrict__ b2,
    float2* __restrict__ oAdd, float2* __restrict__ oSub, float2* __restrict__ oMul,
    int pos, const float4* __restrict__ shW, const float2* __restrict__ shE)
{
    const int idx = pos * M + PI;
    const float2 A = a2[idx], B = b2[idx];

    // add = a+b on circle, sub = a-b (conj b) -- share the 4 products
    {
        float t1 = A.x * B.x, t2 = A.y * B.y, t3 = A.y * B.x, t4 = A.x * B.y;
        oAdd[idx] = make_float2(t1 - t2, t3 + t4);
        oSub[idx] = make_float2(t1 + t2, t3 - t4);
    }

    // packed sides: lane.x = a-side, lane.y = b-side
    const float2 c2 = make_float2(A.x, B.x);
    const float2 s2 = make_float2(A.y, B.y);

    // logits in log2 domain (tables pre-scaled by TEMP*log2e)
    float2 w[P];
#pragma unroll
    for (int i = 0; i < P; i++) {
        float4 t = shW[OFF + i];
        w[i] = f2fma(c2, make_float2(t.x, t.y), f2mul(s2, make_float2(t.z, t.w)));
    }

    // 4-way-tree max per lane (shortens the serial chain)
    float mxa, mxb;
    if (P >= 4) {
        float a0 = w[0].x, a1 = w[1].x, a2_ = w[2].x, a3 = w[3].x;
        float b0 = w[0].y, b1 = w[1].y, b2_ = w[2].y, b3 = w[3].y;
#pragma unroll
        for (int i = 4; i < P; i++) {
            switch (i & 3) {
                case 0: a0 = fmaxf(a0, w[i].x); b0 = fmaxf(b0, w[i].y); break;
                case 1: a1 = fmaxf(a1, w[i].x); b1 = fmaxf(b1, w[i].y); break;
                case 2: a2_ = fmaxf(a2_, w[i].x); b2_ = fmaxf(b2_, w[i].y); break;
                default: a3 = fmaxf(a3, w[i].x); b3 = fmaxf(b3, w[i].y); break;
            }
        }
        mxa = fmaxf(fmaxf(a0, a1), fmaxf(a2_, a3));
        mxb = fmaxf(fmaxf(b0, b1), fmaxf(b2_, b3));
    } else {
        mxa = w[0].x; mxb = w[0].y;
#pragma unroll
        for (int i = 1; i < P; i++) { mxa = fmaxf(mxa, w[i].x); mxb = fmaxf(mxb, w[i].y); }
    }
    const float2 nm = make_float2(-mxa, -mxb);

    // exp (base-2) + packed sums with dual accumulators
    float2 s0 = make_float2(0.f, 0.f), s1 = make_float2(0.f, 0.f);
#pragma unroll
    for (int i = 0; i < P; i++) {
        float2 arg = f2add(w[i], nm);
        w[i] = make_float2(ex2f(arg.x), ex2f(arg.y));
        if (i & 1) s1 = f2add(s1, w[i]); else s0 = f2add(s0, w[i]);
    }
    const float2 S = f2add(s0, s1);
    const float Sa = S.x, Sb = S.y;

    // dist over residues; i=0 / j=0 contributions collapse onto residue 0
    float dist[P];
    dist[0] = fmaf(w[0].x, Sb, fmaf(w[0].y, Sa, -(w[0].x * w[0].y)));
#pragma unroll
    for (int k = 1; k < P; k++) dist[k] = 0.f;
#pragma unroll
    for (int i = 1; i < P; i++) {
        const float wai = w[i].x;
#pragma unroll
        for (int j = 1; j < P; j++) {
            const int k = (i * j) % P;   // bijection over 1..P-1 per i
            dist[k] = fmaf(wai, w[j].y, dist[k]);
        }
    }

    // re-encode to circle (4 accumulators), normalize by (sum wa)*(sum wb)
    float X0 = 0.f, X1 = 0.f, Y0 = 0.f, Y1 = 0.f;
#pragma unroll
    for (int k = 0; k < P; k++) {
        float2 e = shE[OFF + k];
        if (k & 1) { X1 = fmaf(dist[k], e.x, X1); Y1 = fmaf(dist[k], e.y, Y1); }
        else       { X0 = fmaf(dist[k], e.x, X0); Y0 = fmaf(dist[k], e.y, Y0); }
    }
    const float inv = rcpf(Sa * Sb);
    oMul[idx] = make_float2((X0 + X1) * inv, (Y0 + Y1) * inv);
}

__global__ void __launch_bounds__(128, 4)
circle_kernel(const float* __restrict__ a, const float* __restrict__ b,
              float* __restrict__ out)
{
    __shared__ float4 shW[NTAB];
    __shared__ float2 shE[NTAB];
    for (int i = threadIdx.x; i < NTAB; i += 128) {
        shW[i] = g_tabW[i];
        shE[i] = g_tabE[i];
    }
    __syncthreads();

    const int pos = blockIdx.x * 128 + threadIdx.x;
    if (pos >= NPOS) return;

    const float2* a2 = (const float2*)a;
    const float2* b2 = (const float2*)b;
    float2* oAdd = (float2*)out;
    float2* oSub = oAdd + (size_t)NPOS * M;
    float2* oMul = oSub + (size_t)NPOS * M;

    do_prime< 2, 0,   0>(a2, b2, oAdd, oSub, oMul, pos, shW, shE);
    do_prime< 3, 1,   2>(a2, b2, oAdd, oSub, oMul, pos, shW, shE);
    do_prime< 5, 2,   5>(a2, b2, oAdd, oSub, oMul, pos, shW, shE);
    do_prime< 7, 3,  10>(a2, b2, oAdd, oSub, oMul, pos, shW, shE);
    do_prime<11, 4,  17>(a2, b2, oAdd, oSub, oMul, pos, shW, shE);
    do_prime<13, 5,  28>(a2, b2, oAdd, oSub, oMul, pos, shW, shE);
    do_prime<17, 6,  41>(a2, b2, oAdd, oSub, oMul, pos, shW, shE);
    do_prime<19, 7,  58>(a2, b2, oAdd, oSub, oMul, pos, shW, shE);
    do_prime<23, 8,  77>(a2, b2, oAdd, oSub, oMul, pos, shW, shE);
    do_prime<29, 9, 100>(a2, b2, oAdd, oSub, oMul, pos, shW, shE);
}

extern "C" void kernel_launch(void* const* d_in, const int* in_sizes, int n_in,
                              void* d_out, int out_size) {
    const float* a = (const float*)d_in[0];
    const float* b = (const float*)d_in[1];
    float* out = (float*)d_out;
    init_tables_kernel<<<1, 160>>>();
    circle_kernel<<<NPOS / 128, 128>>>(a, b, out);
}